// round 1
// baseline (speedup 1.0000x reference)
#include <cuda_runtime.h>
#include <math.h>

#define TT 4096
#define II 512
#define HH 1024
#define OO 256

#define REC_GRID 128
#define REC_THREADS 256   // 8 warps; warp w owns hidden unit blockIdx.x*8+w
#define UNITS_PER_CTA 8

// Scratch (allocation-free: __device__ globals)
__device__ float g_gx[4][TT][HH];        // per-gate input projections
__device__ float g_h[(TT + 1) * HH];     // row 0 = h_{-1} = 0, row t+1 = h_t
__device__ unsigned g_bar;               // grid barrier counter (monotonic per launch)

// ---------------------------------------------------------------------------
// init: zero h row 0 and the barrier counter (must run every launch -> graph-safe)
// ---------------------------------------------------------------------------
__global__ void init_kernel() {
    int i = blockIdx.x * blockDim.x + threadIdx.x;
    if (i < HH) g_h[i] = 0.0f;
    if (i == 0) g_bar = 0u;
}

// ---------------------------------------------------------------------------
// C[M,N] = A[M,K] @ B[N,K]^T + bias[N]   (both A and B are K-contiguous)
// 64x64 tile, BK=16, 256 threads, 4x4 microtile per thread.
// ---------------------------------------------------------------------------
__global__ __launch_bounds__(256) void gemm_tn_bias(
    const float* __restrict__ A, const float* __restrict__ B,
    const float* __restrict__ bias, float* __restrict__ C,
    int M, int N, int K)
{
    __shared__ float As[16][68];  // [BK][BM+4] pad keeps float4 rows 16B aligned
    __shared__ float Bs[16][68];

    const int bm = blockIdx.y * 64;
    const int bn = blockIdx.x * 64;
    const int tid = threadIdx.x;

    const int lr = tid >> 2;          // 0..63 : tile row for gmem load
    const int lk = (tid & 3) << 2;    // 0,4,8,12 : k offset for gmem load
    const int tx = tid & 15;          // 0..15 : n micro
    const int ty = tid >> 4;          // 0..15 : m micro

    float acc[4][4] = {};

    for (int k0 = 0; k0 < K; k0 += 16) {
        float4 av = *(const float4*)(A + (size_t)(bm + lr) * K + k0 + lk);
        float4 bv = *(const float4*)(B + (size_t)(bn + lr) * K + k0 + lk);
        __syncthreads();
        As[lk + 0][lr] = av.x; As[lk + 1][lr] = av.y;
        As[lk + 2][lr] = av.z; As[lk + 3][lr] = av.w;
        Bs[lk + 0][lr] = bv.x; Bs[lk + 1][lr] = bv.y;
        Bs[lk + 2][lr] = bv.z; Bs[lk + 3][lr] = bv.w;
        __syncthreads();
#pragma unroll
        for (int kk = 0; kk < 16; kk++) {
            float4 af = *(const float4*)&As[kk][ty * 4];
            float4 bf = *(const float4*)&Bs[kk][tx * 4];
            float am[4] = {af.x, af.y, af.z, af.w};
            float bn_[4] = {bf.x, bf.y, bf.z, bf.w};
#pragma unroll
            for (int i = 0; i < 4; i++)
#pragma unroll
                for (int j = 0; j < 4; j++)
                    acc[i][j] += am[i] * bn_[j];
        }
    }

    const int row = bm + ty * 4;
    const int col = bn + tx * 4;
    float b0 = bias[col + 0], b1 = bias[col + 1], b2 = bias[col + 2], b3 = bias[col + 3];
#pragma unroll
    for (int i = 0; i < 4; i++) {
        float4 out;
        out.x = acc[i][0] + b0;
        out.y = acc[i][1] + b1;
        out.z = acc[i][2] + b2;
        out.w = acc[i][3] + b3;
        *(float4*)&C[(size_t)(row + i) * N + col] = out;
    }
}

// ---------------------------------------------------------------------------
// Persistent recurrence kernel. 128 CTAs (all resident, grid < #SM), 8 warps.
// Warp w of CTA b owns hidden unit u = b*8+w: all 4 gate rows of Wh live in
// that warp's registers (4 x 32 floats per lane). c_u lives in lane-0 regs.
// Per step: coalesced __ldcg of h (L2), 128 FMA/lane, warp butterfly reduce,
// lane 0 does activations + __stcg of h_t, then a monotonic atomic grid barrier.
// ---------------------------------------------------------------------------
__global__ __launch_bounds__(REC_THREADS, 1) void lstm_rec(
    const float* __restrict__ Whf, const float* __restrict__ Whi,
    const float* __restrict__ Whc, const float* __restrict__ Who)
{
    const int w = threadIdx.x >> 5;
    const int l = threadIdx.x & 31;
    const int unit = blockIdx.x * UNITS_PER_CTA + w;

    // Load recurrent weights into registers (once).
    float wf[32], wi[32], wc[32], wo[32];
    {
        const float* rf = Whf + (size_t)unit * HH;
        const float* ri = Whi + (size_t)unit * HH;
        const float* rc = Whc + (size_t)unit * HH;
        const float* ro = Who + (size_t)unit * HH;
#pragma unroll
        for (int i = 0; i < 32; i++) {
            int c = l + 32 * i;
            wf[i] = rf[c]; wi[i] = ri[c]; wc[i] = rc[c]; wo[i] = ro[c];
        }
    }

    float cst = 0.0f;  // cell state for this unit (meaningful in lane 0)

    for (int t = 0; t < TT; t++) {
        const float* hrow = g_h + (size_t)t * HH;

        float af = 0.f, ai = 0.f, ac = 0.f, ao = 0.f;
#pragma unroll
        for (int i = 0; i < 32; i++) {
            float hv = __ldcg(hrow + l + 32 * i);  // coalesced 128B/warp, L2-fresh
            af += wf[i] * hv;
            ai += wi[i] * hv;
            ac += wc[i] * hv;
            ao += wo[i] * hv;
        }
#pragma unroll
        for (int off = 16; off > 0; off >>= 1) {
            af += __shfl_xor_sync(0xffffffffu, af, off);
            ai += __shfl_xor_sync(0xffffffffu, ai, off);
            ac += __shfl_xor_sync(0xffffffffu, ac, off);
            ao += __shfl_xor_sync(0xffffffffu, ao, off);
        }

        if (l == 0) {
            float gf = af + g_gx[0][t][unit];
            float gi = ai + g_gx[1][t][unit];
            float gc = ac + g_gx[2][t][unit];
            float go = ao + g_gx[3][t][unit];
            float f_ = 1.0f / (1.0f + expf(-gf));
            float i_ = 1.0f / (1.0f + expf(-gi));
            float cd = tanhf(gc);
            float o_ = 1.0f / (1.0f + expf(-go));
            cst = f_ * cst + i_ * cd;
            float h_ = o_ * cst;                   // reference omits tanh(c)
            __stcg(&g_h[(size_t)(t + 1) * HH + unit], h_);
        }

        // ---- grid barrier (monotonic counter, reset by init_kernel) ----
        __threadfence();
        __syncthreads();
        if (threadIdx.x == 0) {
            atomicAdd(&g_bar, 1u);
            unsigned tgt = (unsigned)(t + 1) * (unsigned)REC_GRID;
            while (*(volatile unsigned*)&g_bar < tgt) { }
            __threadfence();
        }
        __syncthreads();
    }
}

// ---------------------------------------------------------------------------
extern "C" void kernel_launch(void* const* d_in, const int* in_sizes, int n_in,
                              void* d_out, int out_size)
{
    const float* x   = (const float*)d_in[0];
    const float* Wxf = (const float*)d_in[1];
    const float* Whf = (const float*)d_in[2];
    const float* bf  = (const float*)d_in[3];
    const float* Wxi = (const float*)d_in[4];
    const float* Whi = (const float*)d_in[5];
    const float* bi  = (const float*)d_in[6];
    const float* Wxc = (const float*)d_in[7];
    const float* Whc = (const float*)d_in[8];
    const float* bc  = (const float*)d_in[9];
    const float* Wxo = (const float*)d_in[10];
    const float* Who = (const float*)d_in[11];
    const float* bo  = (const float*)d_in[12];
    const float* Wy  = (const float*)d_in[13];
    const float* by  = (const float*)d_in[14];
    float* y = (float*)d_out;

    void* p_gx = nullptr;
    void* p_h  = nullptr;
    cudaGetSymbolAddress(&p_gx, g_gx);
    cudaGetSymbolAddress(&p_h,  g_h);
    float* gx = (float*)p_gx;
    float* hbuf = (float*)p_h;

    init_kernel<<<4, 256>>>();

    // Input projections: 4 GEMMs [4096,1024] = x[4096,512] @ Wx^T + b
    dim3 g1(HH / 64, TT / 64);
    gemm_tn_bias<<<g1, 256>>>(x, Wxf, bf, gx + 0 * (size_t)TT * HH, TT, HH, II);
    gemm_tn_bias<<<g1, 256>>>(x, Wxi, bi, gx + 1 * (size_t)TT * HH, TT, HH, II);
    gemm_tn_bias<<<g1, 256>>>(x, Wxc, bc, gx + 2 * (size_t)TT * HH, TT, HH, II);
    gemm_tn_bias<<<g1, 256>>>(x, Wxo, bo, gx + 3 * (size_t)TT * HH, TT, HH, II);

    // Sequential recurrence (persistent, weights in registers)
    lstm_rec<<<REC_GRID, REC_THREADS>>>(Whf, Whi, Whc, Who);

    // Output projection: y[4096,256] = hs[4096,1024] @ Wy^T + by
    dim3 g2(OO / 64, TT / 64);
    gemm_tn_bias<<<g2, 256>>>(hbuf + HH, Wy, by, y, TT, OO, HH);
}